// round 2
// baseline (speedup 1.0000x reference)
#include <cuda_runtime.h>
#include <cuda_bf16.h>

// EntNet forward, dead-code-eliminated:
//  - candidate memory (U,V,W, prelu a_mem) is dead in the reference
//  - gate (1+sigmoid(...)) cancels under per-column L2 normalization,
//    so F_i@input, keys, and the sigmoid are dead too.
// Live: s_q = F_q@query; mhat_j = mn_j/||mn_j||; p = softmax(s_q . mhat);
//       u = mhat @ p; y = R @ prelu(s_q + H@u, a_out)

#define D 4096
#define M 1024
#define L 8192
#define SPLITS 64           // D split for column-stat pass
#define ROWS_PER 64         // D / SPLITS

__device__ float g_sq[D];
__device__ float g_u[D];
__device__ float g_v[D];
__device__ float g_c[M];
__device__ float g_pdot[SPLITS * M];
__device__ float g_pss[SPLITS * M];

__device__ __forceinline__ float warp_reduce_sum(float v) {
#pragma unroll
    for (int o = 16; o > 0; o >>= 1) v += __shfl_down_sync(0xFFFFFFFFu, v, o);
    return v;
}

// ---------------------------------------------------------------------------
// K1: s_q[d] = dot(F_q[d,:], query)   (4096 rows x 8192 cols)
// warp-per-row, query staged in shared (32KB), float4 loads, 64 iters/lane
// ---------------------------------------------------------------------------
__global__ __launch_bounds__(256) void k_sq(const float* __restrict__ F,
                                            const float* __restrict__ q) {
    __shared__ float4 shq[L / 4];
    for (int i = threadIdx.x; i < L / 4; i += 256)
        shq[i] = reinterpret_cast<const float4*>(q)[i];
    __syncthreads();

    int warp = threadIdx.x >> 5, lane = threadIdx.x & 31;
    int row = blockIdx.x * 8 + warp;
    const float4* Fr = reinterpret_cast<const float4*>(F + (size_t)row * L);
    float acc = 0.f;
#pragma unroll 8
    for (int i = lane; i < L / 4; i += 32) {
        float4 a = Fr[i];
        float4 b = shq[i];
        acc += a.x * b.x + a.y * b.y + a.z * b.z + a.w * b.w;
    }
    acc = warp_reduce_sum(acc);
    if (lane == 0) g_sq[row] = acc;
}

// ---------------------------------------------------------------------------
// K2: per-column partial dot(s_q, mn[:,j]) and sum-of-squares over a D-slice.
// thread = column j (coalesced along row), blockIdx.y = D-slice.
// ---------------------------------------------------------------------------
__global__ __launch_bounds__(128) void k_colpart(const float* __restrict__ mn) {
    int j = blockIdx.x * 128 + threadIdx.x;   // 8 x-blocks cover M=1024
    int s = blockIdx.y;                       // 64 slices of 64 rows
    __shared__ float shq[ROWS_PER];
    if (threadIdx.x < ROWS_PER) shq[threadIdx.x] = g_sq[s * ROWS_PER + threadIdx.x];
    __syncthreads();

    const float* base = mn + (size_t)s * ROWS_PER * M + j;
    float dot = 0.f, ss = 0.f;
#pragma unroll 8
    for (int d = 0; d < ROWS_PER; ++d) {
        float v = base[(size_t)d * M];
        dot += v * shq[d];
        ss  += v * v;
    }
    g_pdot[s * M + j] = dot;
    g_pss [s * M + j] = ss;
}

// ---------------------------------------------------------------------------
// K3: reduce partials, softmax over M, fold 1/norm into c_j = p_j / ||mn_j||.
// Single block of 1024 threads (deterministic, no atomics).
// ---------------------------------------------------------------------------
__global__ __launch_bounds__(1024) void k_softmax() {
    int j = threadIdx.x;
    float dot = 0.f, ss = 0.f;
#pragma unroll 8
    for (int s = 0; s < SPLITS; ++s) {
        dot += g_pdot[s * M + j];
        ss  += g_pss [s * M + j];
    }
    float norm = fmaxf(sqrtf(ss), 1e-12f);
    float t = dot / norm;

    __shared__ float red[32];
    __shared__ float bcast;
    int lane = j & 31, wid = j >> 5;

    // block max
    float m = t;
#pragma unroll
    for (int o = 16; o > 0; o >>= 1) m = fmaxf(m, __shfl_down_sync(0xFFFFFFFFu, m, o));
    if (lane == 0) red[wid] = m;
    __syncthreads();
    if (wid == 0) {
        float x = red[lane];
#pragma unroll
        for (int o = 16; o > 0; o >>= 1) x = fmaxf(x, __shfl_down_sync(0xFFFFFFFFu, x, o));
        if (lane == 0) bcast = x;
    }
    __syncthreads();
    float tmax = bcast;

    float e = expf(t - tmax);

    // block sum
    float su = warp_reduce_sum(e);
    __syncthreads();
    if (lane == 0) red[wid] = su;
    __syncthreads();
    if (wid == 0) {
        float x = red[lane];
        x = warp_reduce_sum(x);
        if (lane == 0) bcast = x;
    }
    __syncthreads();
    float esum = bcast;

    g_c[j] = e / (esum * norm);
}

// ---------------------------------------------------------------------------
// K4: u[d] = dot(mn[d,:], c)   (4096 rows x 1024 cols), warp-per-row
// ---------------------------------------------------------------------------
__global__ __launch_bounds__(256) void k_u(const float* __restrict__ mn) {
    __shared__ float4 shc[M / 4];
    for (int i = threadIdx.x; i < M / 4; i += 256)
        shc[i] = reinterpret_cast<const float4*>(g_c)[i];
    __syncthreads();

    int warp = threadIdx.x >> 5, lane = threadIdx.x & 31;
    int row = blockIdx.x * 8 + warp;
    const float4* r = reinterpret_cast<const float4*>(mn + (size_t)row * M);
    float acc = 0.f;
#pragma unroll
    for (int i = lane; i < M / 4; i += 32) {
        float4 a = r[i];
        float4 b = shc[i];
        acc += a.x * b.x + a.y * b.y + a.z * b.z + a.w * b.w;
    }
    acc = warp_reduce_sum(acc);
    if (lane == 0) g_u[row] = acc;
}

// ---------------------------------------------------------------------------
// K5: v[d] = prelu(s_q[d] + dot(H[d,:], u), a_out)   (4096x4096)
// ---------------------------------------------------------------------------
__global__ __launch_bounds__(256) void k_v(const float* __restrict__ H,
                                           const float* __restrict__ a_out) {
    __shared__ float4 shu[D / 4];
    for (int i = threadIdx.x; i < D / 4; i += 256)
        shu[i] = reinterpret_cast<const float4*>(g_u)[i];
    __syncthreads();

    int warp = threadIdx.x >> 5, lane = threadIdx.x & 31;
    int row = blockIdx.x * 8 + warp;
    const float4* Hr = reinterpret_cast<const float4*>(H + (size_t)row * D);
    float acc = 0.f;
#pragma unroll 8
    for (int i = lane; i < D / 4; i += 32) {
        float4 a = Hr[i];
        float4 b = shu[i];
        acc += a.x * b.x + a.y * b.y + a.z * b.z + a.w * b.w;
    }
    acc = warp_reduce_sum(acc);
    if (lane == 0) {
        float x = g_sq[row] + acc;
        float a = a_out[0];
        g_v[row] = (x >= 0.f) ? x : a * x;
    }
}

// ---------------------------------------------------------------------------
// K6: y[d] = dot(R[d,:], v)   (4096x4096) -> d_out
// ---------------------------------------------------------------------------
__global__ __launch_bounds__(256) void k_y(const float* __restrict__ R,
                                           float* __restrict__ out) {
    __shared__ float4 shv[D / 4];
    for (int i = threadIdx.x; i < D / 4; i += 256)
        shv[i] = reinterpret_cast<const float4*>(g_v)[i];
    __syncthreads();

    int warp = threadIdx.x >> 5, lane = threadIdx.x & 31;
    int row = blockIdx.x * 8 + warp;
    const float4* Rr = reinterpret_cast<const float4*>(R + (size_t)row * D);
    float acc = 0.f;
#pragma unroll 8
    for (int i = lane; i < D / 4; i += 32) {
        float4 a = Rr[i];
        float4 b = shv[i];
        acc += a.x * b.x + a.y * b.y + a.z * b.z + a.w * b.w;
    }
    acc = warp_reduce_sum(acc);
    if (lane == 0) out[row] = acc;
}

extern "C" void kernel_launch(void* const* d_in, const int* in_sizes, int n_in,
                              void* d_out, int out_size) {
    // metadata order: input, query, F_i, F_q, keys, memory_nodes, U, V, W, R, H, a_mem, a_out
    const float* query = (const float*)d_in[1];
    const float* F_q   = (const float*)d_in[3];
    const float* mn    = (const float*)d_in[5];
    const float* Rm    = (const float*)d_in[9];
    const float* Hm    = (const float*)d_in[10];
    const float* a_out = (const float*)d_in[12];
    float* out = (float*)d_out;

    k_sq<<<D / 8, 256>>>(F_q, query);
    dim3 g2(M / 128, SPLITS);
    k_colpart<<<g2, 128>>>(mn);
    k_softmax<<<1, 1024>>>();
    k_u<<<D / 8, 256>>>(mn);
    k_v<<<D / 8, 256>>>(Hm, a_out);
    k_y<<<D / 8, 256>>>(Rm, out);
}